// round 7
// baseline (speedup 1.0000x reference)
#include <cuda_runtime.h>
#include <cuda_fp16.h>

#define BB 4
#define SS 512
#define HH 256
#define H4 (HH / 4)        // 64 groups of 4 h-elements

// Scratch (allocation-free rule -> __device__ globals)
__device__ __half g_ht_h[BB * SS * HH];      // [bt][h]   ht + b_h, half
__device__ uint2  g_htpT[BB * H4 * SS];      // [b][h4][tp] 4 packed halves of htp
__device__ float  g_p[BB * SS * SS];         // unnormalized exp(sigmoid(score))

__device__ __forceinline__ float tanh_fast(float x) {
    float y; asm("tanh.approx.f32 %0, %1;" : "=f"(y) : "f"(x)); return y;
}
__device__ __forceinline__ unsigned tanh2u(unsigned x) {
    unsigned y; asm("tanh.approx.f16x2 %0, %1;" : "=r"(y) : "r"(x)); return y;
}
__device__ __forceinline__ __half2 u2h(unsigned x) { return *reinterpret_cast<__half2*>(&x); }
__device__ __forceinline__ unsigned h2u(__half2 x) { return *reinterpret_cast<unsigned*>(&x); }

__device__ __forceinline__ void cp_async16(void* smem_dst, const void* gmem_src) {
    unsigned saddr = (unsigned)__cvta_generic_to_shared(smem_dst);
    asm volatile("cp.async.cg.shared.global [%0], [%1], 16;" :: "r"(saddr), "l"(gmem_src));
}
__device__ __forceinline__ void cp_commit() {
    asm volatile("cp.async.commit_group;");
}
template <int N>
__device__ __forceinline__ void cp_wait() {
    asm volatile("cp.async.wait_group %0;" :: "n"(N));
}

// ---------------------------------------------------------------------------
// Stage 1: projections, 512 threads (half 0: Wt, half 1: Wtp).
// v4: W streamed through smem with cp.async double buffering (32 tiles of
// 8 hh rows, 16KB/tile). Inner loop reads W from smem -> no exposed L2
// latency; FFMA-issue bound.
// ---------------------------------------------------------------------------
__global__ void __launch_bounds__(512)
proj_kernel(const float* __restrict__ h,
            const float* __restrict__ Wt,
            const float* __restrict__ Wtp,
            const float* __restrict__ bh)
{
    constexpr int ROWS = 8;
    constexpr int THH  = 8;                    // hh rows per tile
    constexpr int NT   = HH / THH;             // 32 tiles
    __shared__ float sh[ROWS][HH];             // 8KB
    __shared__ float sW[2][2][THH][HH];        // [buf][half][hh][k] 32KB

    const int row0 = blockIdx.x * ROWS;
    const int tid  = threadIdx.x;
    const int half = tid >> 8;          // 0: Wt, 1: Wtp
    const int k    = tid & 255;

    for (int i = tid; i < ROWS * HH; i += 512)
        sh[i >> 8][i & 255] = h[row0 * HH + i];

    // Tile copy helper mapping: float4 f in [0,1024): half=f/512, hh=(f%512)/64, k4=f%64
    const float* __restrict__ Wsrc[2] = { Wt, Wtp };
    {
        // preload tile 0 into buf 0
#pragma unroll
        for (int pass = 0; pass < 2; ++pass) {
            const int f  = tid + pass * 512;
            const int hf = f >> 9;
            const int hhq= (f >> 6) & 7;
            const int k4 = f & 63;
            cp_async16(&sW[0][hf][hhq][k4 * 4],
                       Wsrc[hf] + (0 * THH + hhq) * HH + k4 * 4);
        }
        cp_commit();
    }

    float acc[ROWS];
#pragma unroll
    for (int r = 0; r < ROWS; ++r) acc[r] = 0.f;

    for (int t = 0; t < NT; ++t) {
        if (t + 1 < NT) {
            const int buf = (t + 1) & 1;
#pragma unroll
            for (int pass = 0; pass < 2; ++pass) {
                const int f  = tid + pass * 512;
                const int hf = f >> 9;
                const int hhq= (f >> 6) & 7;
                const int k4 = f & 63;
                cp_async16(&sW[buf][hf][hhq][k4 * 4],
                           Wsrc[hf] + ((t + 1) * THH + hhq) * HH + k4 * 4);
            }
            cp_commit();
            cp_wait<1>();
        } else {
            cp_wait<0>();
        }
        __syncthreads();

        const int buf = t & 1;
        const float* __restrict__ sWp = &sW[buf][half][0][k];
        const int hh0 = t * THH;
#pragma unroll
        for (int q = 0; q < THH; q += 4) {
            const float w0 = sWp[(q + 0) * HH];
            const float w1 = sWp[(q + 1) * HH];
            const float w2 = sWp[(q + 2) * HH];
            const float w3 = sWp[(q + 3) * HH];
#pragma unroll
            for (int r = 0; r < ROWS; ++r) {
                const float4 hv = *reinterpret_cast<const float4*>(&sh[r][hh0 + q]);
                acc[r] = fmaf(hv.x, w0, acc[r]);
                acc[r] = fmaf(hv.y, w1, acc[r]);
                acc[r] = fmaf(hv.z, w2, acc[r]);
                acc[r] = fmaf(hv.w, w3, acc[r]);
            }
        }
        __syncthreads();
    }

    if (half == 0) {
        const float bias = bh[k];
#pragma unroll
        for (int r = 0; r < ROWS; ++r)
            g_ht_h[(row0 + r) * HH + k] = __float2half(acc[r] + bias);
    } else {
        __half* htpT = reinterpret_cast<__half*>(g_htpT);
#pragma unroll
        for (int r = 0; r < ROWS; ++r) {
            const int row = row0 + r;
            const int b   = row >> 9;
            const int tp  = row & (SS - 1);
            htpT[(((size_t)b * H4 + (k >> 2)) * SS + tp) * 4 + (k & 3)] = __float2half(acc[r]);
        }
    }
}

// ---------------------------------------------------------------------------
// Stage 2: pure (t, tp) score map, no normalization. (unchanged)
//   p[bt][tp] = exp(sigmoid(Wa . tanh(ht[t] + htp[tp]) + ba))
// ---------------------------------------------------------------------------
__global__ void __launch_bounds__(256)
score_kernel(const float* __restrict__ Wa,
             const float* __restrict__ ba)
{
    const int bt0 = blockIdx.y * 16;        // 16 rows, same batch (16 | 512)
    const int b   = bt0 >> 9;
    const int tid = threadIdx.x;
    const int w   = tid >> 5;
    const int lane= tid & 31;

    __shared__ uint4 su[16][H4];            // {ht01, ht23, wa01, wa23}  16KB

    for (int e = tid; e < 16 * H4; e += 256) {
        const int t  = e >> 6;
        const int h4 = e & 63;
        const uint2 ht4 = reinterpret_cast<const uint2*>(g_ht_h)[(bt0 + t) * (HH / 4) + h4];
        const float4 wa4 = reinterpret_cast<const float4*>(Wa)[h4];
        su[t][h4] = make_uint4(ht4.x, ht4.y,
                               h2u(__floats2half2_rn(wa4.x, wa4.y)),
                               h2u(__floats2half2_rn(wa4.z, wa4.w)));
    }
    __syncthreads();

    const float bav = ba[0];
    const int   tp  = blockIdx.x * 32 + lane;
    const int   r0  = 2 * w, r1 = 2 * w + 1;
    const uint2* hp = g_htpT + (size_t)b * H4 * SS + tp;

    float fa0 = 0.f, fa1 = 0.f;
    __half2 z = __floats2half2_rn(0.f, 0.f);
    __half2 acc0 = z, acc1 = z;

#pragma unroll 1
    for (int hb = 0; hb < 16; ++hb) {       // fold to fp32 every 4 h4
#pragma unroll
        for (int j = 0; j < 4; ++j) {
            const int h4 = hb * 4 + j;
            const uint2 x  = hp[(size_t)h4 * SS];
            const __half2 xa = u2h(x.x), xb = u2h(x.y);
            const uint4 u0 = su[r0][h4];
            const uint4 u1 = su[r1][h4];
            acc0 = __hfma2(u2h(u0.z), u2h(tanh2u(h2u(__hadd2(u2h(u0.x), xa)))), acc0);
            acc0 = __hfma2(u2h(u0.w), u2h(tanh2u(h2u(__hadd2(u2h(u0.y), xb)))), acc0);
            acc1 = __hfma2(u2h(u1.z), u2h(tanh2u(h2u(__hadd2(u2h(u1.x), xa)))), acc1);
            acc1 = __hfma2(u2h(u1.w), u2h(tanh2u(h2u(__hadd2(u2h(u1.y), xb)))), acc1);
        }
        const float2 f0 = __half22float2(acc0);
        const float2 f1 = __half22float2(acc1);
        fa0 += f0.x + f0.y;
        fa1 += f1.x + f1.y;
        acc0 = z; acc1 = z;
    }

    const float s0 = fa0 + bav;
    const float s1 = fa1 + bav;
    const float p0 = __expf(0.5f * tanh_fast(0.5f * s0) + 0.5f);
    const float p1 = __expf(0.5f * tanh_fast(0.5f * s1) + 0.5f);
    g_p[(size_t)(bt0 + r0) * SS + tp] = p0;
    g_p[(size_t)(bt0 + r1) * SS + tp] = p1;
}

// ---------------------------------------------------------------------------
// Stage 3: rowsum + normalize + output GEMM, 512 threads. (unchanged)
// ---------------------------------------------------------------------------
__global__ void __launch_bounds__(512)
out_kernel(const float* __restrict__ hin,
           float* __restrict__ out,
           float* __restrict__ wts)
{
    const int bt0 = blockIdx.x * 8;
    const int b   = bt0 >> 9;
    const int tid = threadIdx.x;
    const int w   = tid >> 5;
    const int lane= tid & 31;
    const int seg = tid >> 8;           // 0 or 1 (tp half)
    const int k   = tid & 255;

    __shared__ float pT[SS][8];             // transposed p (unnormalized)  16KB
    __shared__ float part[8][HH];           // seg-1 partial sums           8KB
    __shared__ float rinv[8];

    // Load p coalesced, store transposed.
    for (int e = tid; e < 8 * SS; e += 512) {
        const int t  = e >> 9;
        const int tp = e & (SS - 1);
        pT[tp][t] = g_p[(size_t)(bt0 + t) * SS + tp];
    }
    __syncthreads();

    // Rowsum: warps 0..7 own rows 0..7.
    if (w < 8) {
        float s = 0.f;
        for (int tp = lane; tp < SS; tp += 32) s += pT[tp][w];
#pragma unroll
        for (int off = 16; off > 0; off >>= 1)
            s += __shfl_xor_sync(0xffffffffu, s, off);
        if (lane == 0) rinv[w] = 1.0f / s;
    }
    __syncthreads();

    // Normalized weights output.
    if (wts) {
        for (int e = tid; e < 8 * SS; e += 512) {
            const int t  = e >> 9;
            const int tp = e & (SS - 1);
            wts[(size_t)(bt0 + t) * SS + tp] = pT[tp][t] * rinv[t];
        }
    }

    // GEMM with unnormalized p over this segment's tp range.
    float facc[8];
#pragma unroll
    for (int r = 0; r < 8; ++r) facc[r] = 0.f;
    const float* hb = hin + (size_t)b * SS * HH + k;
    const int tp0 = seg * 256;
#pragma unroll 4
    for (int i = 0; i < 256; ++i) {
        const int tp = tp0 + i;
        const float hv = hb[(size_t)tp * HH];
        const float4 wA = *reinterpret_cast<const float4*>(&pT[tp][0]);
        const float4 wB = *reinterpret_cast<const float4*>(&pT[tp][4]);
        facc[0] = fmaf(wA.x, hv, facc[0]);
        facc[1] = fmaf(wA.y, hv, facc[1]);
        facc[2] = fmaf(wA.z, hv, facc[2]);
        facc[3] = fmaf(wA.w, hv, facc[3]);
        facc[4] = fmaf(wB.x, hv, facc[4]);
        facc[5] = fmaf(wB.y, hv, facc[5]);
        facc[6] = fmaf(wB.z, hv, facc[6]);
        facc[7] = fmaf(wB.w, hv, facc[7]);
    }

    if (seg == 1) {
#pragma unroll
        for (int r = 0; r < 8; ++r) part[r][k] = facc[r];
    }
    __syncthreads();
    if (seg == 0) {
#pragma unroll
        for (int r = 0; r < 8; ++r)
            out[(size_t)(bt0 + r) * HH + k] = (facc[r] + part[r][k]) * rinv[r];
    }
}

// ---------------------------------------------------------------------------
extern "C" void kernel_launch(void* const* d_in, const int* in_sizes, int n_in,
                              void* d_out, int out_size)
{
    const float* h   = (const float*)d_in[0];
    const float* Wt  = (const float*)d_in[1];
    const float* Wtp = (const float*)d_in[2];
    const float* bh  = (const float*)d_in[3];
    const float* Wa  = (const float*)d_in[4];
    const float* ba  = (const float*)d_in[5];

    float* out = (float*)d_out;
    float* wts = nullptr;
    const int nOut = BB * SS * HH;   // 524288
    const int nW   = BB * SS * SS;   // 1048576
    if (out_size >= nOut + nW) wts = out + nOut;

    proj_kernel<<<BB * SS / 8, 512>>>(h, Wt, Wtp, bh);
    score_kernel<<<dim3(SS / 32, BB * SS / 16), 256>>>(Wa, ba);
    out_kernel<<<BB * SS / 8, 512>>>(h, out, wts);
}